// round 15
// baseline (speedup 1.0000x reference)
#include <cuda_runtime.h>
#include <cuda_fp16.h>
#include <cstdint>

// ---------------------------------------------------------------------------
// LMPNN round 15: R14 + v-half-split tile processing. accS live range 64->32
// regs so ptxas regains scheduling slack to pipeline LDSM ahead of MMA groups.
// Per tile: for vh in {0,1}: GEMM1(vh) -> per-g epilogue+GEMM2(vh).
// ---------------------------------------------------------------------------

#define DD 128
static constexpr int N_NODES = 4096;
static constexpr int N_EDGES = 262144;
static constexpr int N_ENT   = 50000;
static constexpr int N_REL   = 1000;

static constexpr int BM = 128;
static constexpr int BV = 128;
static constexpr int NVT = (N_ENT + BV - 1) / BV;        // 391
static constexpr int NSPLIT = 9;
static constexpr int TPS = (NVT + NSPLIT - 1) / NSPLIT;  // 44
static constexpr int MTILES = N_NODES / BM;              // 32
static constexpr int NTHR = 128;                         // 4 warps x 32 rows

__device__ float  g_aggr[N_NODES * DD];
__device__ __half g_Eh[(size_t)N_ENT * DD];
__device__ __half g_xh[N_NODES * DD];
__device__ __half g_relh[N_REL * DD];
__device__ __half g_sch[N_ENT];
__device__ __half g_bih[N_ENT];

// ---- smem map (bytes) ------------------------------------------------------
static constexpr int SM_A  = 0;           // 32768  A [128m,128k] fp16
static constexpr int SM_EB = 32768;       // 2 bufs x 33280
static constexpr int EB_E   = 0;          // 32768  E [128v,128d] fp16
static constexpr int EB_SCB = 32768;      // 512 (128 sc f16 + 128 bi f16)
static constexpr int EB_STRIDE = 33280;
static constexpr int SMEM_BYTES = 32768 + 2 * EB_STRIDE;  // 99328; x2/SM ok

// ---------------------------------------------------------------------------
__device__ __forceinline__ uint32_t s2u(const void* p) {
    uint32_t a;
    asm("{ .reg .u64 t; cvta.to.shared.u64 t, %1; cvt.u32.u64 %0, t; }" : "=r"(a) : "l"(p));
    return a;
}
// swizzled offsets: 16B chunks XOR'ed by (row & 7); rows of 128 f16 (256B)
__device__ __forceinline__ uint32_t off128(int r, int c) {
    return (uint32_t)(r * 256) + ((((c >> 3) ^ (r & 7)) << 4) | ((c & 7) * 2));
}
__device__ __forceinline__ void cpa16(uint32_t dst, const void* src, int srcsize) {
    asm volatile("cp.async.cg.shared.global [%0], [%1], 16, %2;"
                 :: "r"(dst), "l"(src), "r"(srcsize) : "memory");
}
__device__ __forceinline__ void cpa_commit() { asm volatile("cp.async.commit_group;" ::: "memory"); }
__device__ __forceinline__ void cpa_wait0()  { asm volatile("cp.async.wait_group 0;"  ::: "memory"); }

__device__ __forceinline__ void ldm4(uint32_t& r0, uint32_t& r1, uint32_t& r2, uint32_t& r3, uint32_t a) {
    asm volatile("ldmatrix.sync.aligned.m8n8.x4.shared.b16 {%0,%1,%2,%3}, [%4];"
                 : "=r"(r0), "=r"(r1), "=r"(r2), "=r"(r3) : "r"(a));
}
__device__ __forceinline__ void ldm4t(uint32_t& r0, uint32_t& r1, uint32_t& r2, uint32_t& r3, uint32_t a) {
    asm volatile("ldmatrix.sync.aligned.m8n8.x4.trans.shared.b16 {%0,%1,%2,%3}, [%4];"
                 : "=r"(r0), "=r"(r1), "=r"(r2), "=r"(r3) : "r"(a));
}
// f32-accumulator MMA (GEMM2)
__device__ __forceinline__ void mma16816h(float* d, const uint32_t* a, const uint32_t* b) {
    asm volatile("mma.sync.aligned.m16n8k16.row.col.f32.f16.f16.f32 "
                 "{%0,%1,%2,%3}, {%4,%5,%6,%7}, {%8,%9}, {%0,%1,%2,%3};"
                 : "+f"(d[0]), "+f"(d[1]), "+f"(d[2]), "+f"(d[3])
                 : "r"(a[0]), "r"(a[1]), "r"(a[2]), "r"(a[3]), "r"(b[0]), "r"(b[1]));
}
// f16-accumulator MMA (GEMM1): D regs are f16x2 {c0,c1},{c2,c3}
__device__ __forceinline__ void mma16816hh(uint32_t* d, const uint32_t* a, const uint32_t* b) {
    asm volatile("mma.sync.aligned.m16n8k16.row.col.f16.f16.f16.f16 "
                 "{%0,%1}, {%2,%3,%4,%5}, {%6,%7}, {%0,%1};"
                 : "+r"(d[0]), "+r"(d[1])
                 : "r"(a[0]), "r"(a[1]), "r"(a[2]), "r"(a[3]), "r"(b[0]), "r"(b[1]));
}
__device__ __forceinline__ void red_add_v2(float* p, float a, float b) {
    asm volatile("red.global.add.v2.f32 [%0], {%1, %2};" :: "l"(p), "f"(a), "f"(b) : "memory");
}
__device__ __forceinline__ void red_add_v4(float* p, float a, float b, float c, float d) {
    asm volatile("red.global.add.v4.f32 [%0], {%1, %2, %3, %4};"
                 :: "l"(p), "f"(a), "f"(b), "f"(c), "f"(d) : "memory");
}
__device__ __forceinline__ uint32_t pack_h2(float a, float b) {
    uint32_t p;
    asm("cvt.rn.f16x2.f32 %0, %1, %2;" : "=r"(p) : "f"(b), "f"(a));
    return p;
}
__device__ __forceinline__ float2 unpack_h2(uint32_t p) {
    __half2 h = *reinterpret_cast<__half2*>(&p);
    return __half22float2(h);
}
__device__ __forceinline__ uint32_t hfma2_relu(uint32_t s, uint32_t sc, uint32_t bi) {
    uint32_t d;
    asm("fma.rn.f16x2 %0, %1, %2, %3;" : "=r"(d) : "r"(s), "r"(sc), "r"(bi));
    asm("max.f16x2 %0, %0, %1;" : "+r"(d) : "r"(0u));
    return d;
}

// ---------------------------------------------------------------------------
// prepA: x/rel -> fp16, g_aggr = 0.1x, out = 0
static constexpr int PA_X = N_NODES * (DD / 2);   // 262144 f2 units
static constexpr int PA_R = N_REL * (DD / 2);     // 64000

__global__ void prepA_kernel(const float* __restrict__ x,
                             const float* __restrict__ rel,
                             float* __restrict__ out) {
    int i = blockIdx.x * blockDim.x + threadIdx.x;
    if (i >= PA_X) return;
    float2 v = ((const float2*)x)[i];
    ((uint32_t*)g_xh)[i] = pack_h2(v.x, v.y);
    ((float2*)g_aggr)[i] = make_float2(0.1f * v.x, 0.1f * v.y);
    ((float2*)out)[i] = make_float2(0.f, 0.f);
    if (i < PA_R) {
        float2 r = ((const float2*)rel)[i];
        ((uint32_t*)g_relh)[i] = pack_h2(r.x, r.y);
    }
}

// combo: scatter (blocks [0, SCAT_BLK)) + E/scale/bias fp16 convert (rest)
static constexpr int SCAT_BLK = N_EDGES * 32 / 256;   // 32768
static constexpr int CV_E  = N_ENT * (DD / 2);        // 3,200,000 u32 items
static constexpr int CV_SC = N_ENT / 2;               // 25,000
static constexpr int CV_TOT = CV_E + 2 * CV_SC;       // 3,250,000
static constexpr int CV_BLK = (CV_TOT + 255) / 256;   // 12696

__global__ void combo_kernel(const int* __restrict__ eidx,
                             const int* __restrict__ rid, const int* __restrict__ neg,
                             const float* __restrict__ eemb,
                             const float* __restrict__ scal,
                             const float* __restrict__ bias) {
    if (blockIdx.x < SCAT_BLK) {
        int gw = (blockIdx.x * blockDim.x + threadIdx.x) >> 5;
        int lane = threadIdx.x & 31;
        int src = eidx[gw], dst = eidx[N_EDGES + gw], r = rid[gw];
        float coef = 1.0f - 2.0f * (float)neg[gw];
        uint2 xv = ((const uint2*)(g_xh   + (size_t)src * DD))[lane];
        uint2 rv = ((const uint2*)(g_relh + (size_t)r   * DD))[lane];
        float2 x01 = unpack_h2(xv.x), x23 = unpack_h2(xv.y);
        float2 r01 = unpack_h2(rv.x), r23 = unpack_h2(rv.y);
        red_add_v4(g_aggr + (size_t)dst * DD + lane * 4,
                   (x01.x + r01.x) * coef, (x01.y + r01.y) * coef,
                   (x23.x + r23.x) * coef, (x23.y + r23.y) * coef);
    } else {
        int j = (blockIdx.x - SCAT_BLK) * 256 + threadIdx.x;
        if (j < CV_E) {
            float2 v = ((const float2*)eemb)[j];
            ((uint32_t*)g_Eh)[j] = pack_h2(v.x, v.y);
        } else if (j < CV_E + CV_SC) {
            int k = j - CV_E;
            float2 v = ((const float2*)scal)[k];
            ((uint32_t*)g_sch)[k] = pack_h2(v.x, v.y);
        } else if (j < CV_TOT) {
            int k = j - CV_E - CV_SC;
            float2 v = ((const float2*)bias)[k];
            ((uint32_t*)g_bih)[k] = pack_h2(v.x, v.y);
        }
    }
}

// ---------------------------------------------------------------------------
__global__ void __launch_bounds__(NTHR, 2)
gemm_fused(float* __restrict__ out) {
    extern __shared__ char smem[];
    const uint32_t sb = s2u(smem);
    const int tid = threadIdx.x, wid = tid >> 5, lane = tid & 31;
    const int mt = blockIdx.x & (MTILES - 1), sp = blockIdx.x / MTILES;
    const int m0 = mt * BM;
    const int t0 = sp * TPS, t1 = min(NVT, t0 + TPS);
    if (t0 >= t1) return;

    const int wm = wid * 32;               // warp owns rows [wm, wm+32): 2 m16

    auto load_tiles = [&](int t, int b) {
        const int v0 = t * BV;
        const uint32_t eb = sb + SM_EB + b * EB_STRIDE;
        for (int i = tid; i < 2048; i += NTHR) {    // E [128v,128d] fp16, 16B chunks
            int v = i >> 4, dg = (i & 15) * 8;
            int gv = v0 + v;
            uint32_t o = off128(v, dg);
            int sz = (gv < N_ENT) ? 16 : 0;
            const void* pE = sz ? (const void*)(g_Eh + (size_t)gv * DD + dg) : (const void*)g_Eh;
            cpa16(eb + EB_E + o, pE, sz);
        }
        if (tid < 32) {                              // 128 sc f16 + 128 bi f16
            int half = tid >> 4, g = tid & 15;       // 16 x 16B per array
            int gv = v0 + g * 8;
            int rem = N_ENT - gv;
            int sz = rem >= 8 ? 16 : (rem > 0 ? rem * 2 : 0);
            const __half* src = half ? g_bih : g_sch;
            const void* p = sz ? (const void*)(src + gv) : (const void*)src;
            cpa16(eb + EB_SCB + half * 256 + g * 16, p, sz);
        }
    };

    // issue tile-0 E loads first so they overlap the A staging below
    load_tiles(t0, 0);
    cpa_commit();

    // ---- A tile: g_aggr f32 -> fp16, swizzled (staged once) ----
    for (int i = tid; i < BM * (DD / 4); i += NTHR) {
        int m = i >> 5, k = (i & 31) * 4;
        float4 a = *(const float4*)(g_aggr + (size_t)(m0 + m) * DD + k);
        *(uint32_t*)(smem + SM_A + off128(m, k))     = pack_h2(a.x, a.y);
        *(uint32_t*)(smem + SM_A + off128(m, k + 2)) = pack_h2(a.z, a.w);
    }
    __syncthreads();

    // per-lane ldmatrix pieces (constant across loop)
    const int lr16 = lane & 15;            // row within 16
    const int lc8  = (lane >> 4) << 3;     // +8 col for upper half-warp
    const int lrB  = (lane & 7) | ((lane & 16) >> 1);  // B non-trans row
    const int lcB  = lane & 8;                          // B non-trans col sel
    const int ce   = (lane & 3) * 2;       // C/epilogue col pair base

    float accO[2][16][4];                   // 2 m16 x 128d per warp
    #pragma unroll
    for (int mi = 0; mi < 2; mi++)
        #pragma unroll
        for (int nt = 0; nt < 16; nt++)
            #pragma unroll
            for (int q = 0; q < 4; q++) accO[mi][nt][q] = 0.0f;

    for (int t = t0; t < t1; ++t) {
        const int buf = (t - t0) & 1;
        const uint32_t eb = sb + SM_EB + buf * EB_STRIDE;

        cpa_wait0();           // tile t landed (this thread's copies)
        __syncthreads();       // visible to all; all warps done with buf^1
        if (t + 1 < t1) { load_tiles(t + 1, buf ^ 1); cpa_commit(); }

        const __half* sch = (const __half*)(smem + SM_EB + buf * EB_STRIDE + EB_SCB);

        // ---- per v-half: GEMM1 -> per-g epilogue + GEMM2 --------------------
        #pragma unroll
        for (int vh = 0; vh < 2; vh++) {
            // GEMM1: S[32m x 64v(vh)] per warp, fp16 accumulators
            uint32_t accS[2][8][2];
            #pragma unroll
            for (int mi = 0; mi < 2; mi++)
                #pragma unroll
                for (int nt = 0; nt < 8; nt++)
                    accS[mi][nt][0] = accS[mi][nt][1] = 0u;

            #pragma unroll
            for (int ks = 0; ks < 8; ks++) {
                const int k0 = ks * 16;
                uint32_t aA[2][4];
                #pragma unroll
                for (int mi = 0; mi < 2; mi++) {
                    uint32_t o = off128(wm + mi * 16 + lr16, k0 + lc8);
                    ldm4(aA[mi][0], aA[mi][1], aA[mi][2], aA[mi][3], sb + SM_A + o);
                }
                uint32_t bF[8][2];
                #pragma unroll
                for (int ng = 0; ng < 4; ng++) {
                    uint32_t o = off128(vh * 64 + ng * 16 + lrB, k0 + lcB);
                    uint32_t r0, r1, r2, r3;
                    ldm4(r0, r1, r2, r3, eb + EB_E + o);
                    bF[ng * 2][0] = r0; bF[ng * 2][1] = r1;
                    bF[ng * 2 + 1][0] = r2; bF[ng * 2 + 1][1] = r3;
                }
                #pragma unroll
                for (int mi = 0; mi < 2; mi++)
                    #pragma unroll
                    for (int nt = 0; nt < 8; nt++)
                        mma16816hh(accS[mi][nt], aA[mi], bF[nt]);
            }

            // per-g: packed f16x2 epilogue -> GEMM2 for k16 group (vh*4+g2)
            #pragma unroll
            for (int g2 = 0; g2 < 4; g2++) {
                uint32_t aS[2][4];
                #pragma unroll
                for (int sub2 = 0; sub2 < 2; sub2++) {   // nt = 2*g2, 2*g2+1
                    const int nt = 2 * g2 + sub2;
                    const int c = vh * 64 + nt * 8 + ce;
                    uint32_t sc2 = *(const uint32_t*)(sch + c);
                    uint32_t bi2 = *(const uint32_t*)(sch + 128 + c);
                    #pragma unroll
                    for (int mi = 0; mi < 2; mi++) {
                        aS[mi][sub2 * 2]     = hfma2_relu(accS[mi][nt][0], sc2, bi2);
                        aS[mi][sub2 * 2 + 1] = hfma2_relu(accS[mi][nt][1], sc2, bi2);
                    }
                }
                const int k0 = vh * 64 + g2 * 16;
                #pragma unroll
                for (int half = 0; half < 2; half++) {
                    uint32_t bF[8][2];
                    #pragma unroll
                    for (int ng = 0; ng < 4; ng++) {
                        uint32_t o = off128(k0 + lr16, half * 64 + ng * 16 + lc8);
                        uint32_t r0, r1, r2, r3;
                        ldm4t(r0, r1, r2, r3, eb + EB_E + o);
                        bF[ng * 2][0] = r0; bF[ng * 2][1] = r1;
                        bF[ng * 2 + 1][0] = r2; bF[ng * 2 + 1][1] = r3;
                    }
                    #pragma unroll
                    for (int mi = 0; mi < 2; mi++)
                        #pragma unroll
                        for (int ng = 0; ng < 8; ng++)
                            mma16816h(accO[mi][half * 8 + ng], aS[mi], bF[ng]);
                }
            }
        }
    }

    // ---- flush O to out (+= across splits) ----
    #pragma unroll
    for (int mi = 0; mi < 2; mi++) {
        const int r0 = m0 + wm + mi * 16 + (lane >> 2);
        #pragma unroll
        for (int nt = 0; nt < 16; nt++) {
            const int c = nt * 8 + ce;
            red_add_v2(out + (size_t)r0 * DD + c,       accO[mi][nt][0], accO[mi][nt][1]);
            red_add_v2(out + (size_t)(r0 + 8) * DD + c, accO[mi][nt][2], accO[mi][nt][3]);
        }
    }
}

// ---------------------------------------------------------------------------
extern "C" void kernel_launch(void* const* d_in, const int* in_sizes, int n_in,
                              void* d_out, int out_size) {
    const float* x     = (const float*)d_in[0];
    const int*   eidx  = (const int*)  d_in[1];
    const int*   rid   = (const int*)  d_in[2];
    const int*   neg   = (const int*)  d_in[3];
    const float* rel   = (const float*)d_in[4];
    const float* eemb  = (const float*)d_in[5];
    const float* scale = (const float*)d_in[6];
    const float* bias  = (const float*)d_in[7];
    float* out = (float*)d_out;

    cudaFuncSetAttribute(gemm_fused, cudaFuncAttributeMaxDynamicSharedMemorySize, SMEM_BYTES);

    prepA_kernel<<<(PA_X + 255) / 256, 256>>>(x, rel, out);
    combo_kernel<<<SCAT_BLK + CV_BLK, 256>>>(eidx, rid, neg, eemb, scale, bias);
    gemm_fused<<<MTILES * NSPLIT, NTHR, SMEM_BYTES>>>(out);
}

// round 16
// speedup vs baseline: 1.0536x; 1.0536x over previous
#include <cuda_runtime.h>
#include <cuda_fp16.h>
#include <cstdint>

// ---------------------------------------------------------------------------
// LMPNN round 16: revert to R14 (best: 259.0us) with the accidental no-op
// ternary in GEMM1's MMA call removed. BM=128, BV=128, fp16 throughout,
// fp16-accum GEMM1, packed f16x2 epilogue, f32-accum GEMM2, 2 CTAs/SM.
// ---------------------------------------------------------------------------

#define DD 128
static constexpr int N_NODES = 4096;
static constexpr int N_EDGES = 262144;
static constexpr int N_ENT   = 50000;
static constexpr int N_REL   = 1000;

static constexpr int BM = 128;
static constexpr int BV = 128;
static constexpr int NVT = (N_ENT + BV - 1) / BV;        // 391
static constexpr int NSPLIT = 9;
static constexpr int TPS = (NVT + NSPLIT - 1) / NSPLIT;  // 44
static constexpr int MTILES = N_NODES / BM;              // 32
static constexpr int NTHR = 128;                         // 4 warps x 32 rows

__device__ float  g_aggr[N_NODES * DD];
__device__ __half g_Eh[(size_t)N_ENT * DD];
__device__ __half g_xh[N_NODES * DD];
__device__ __half g_relh[N_REL * DD];
__device__ __half g_sch[N_ENT];
__device__ __half g_bih[N_ENT];

// ---- smem map (bytes) ------------------------------------------------------
static constexpr int SM_A  = 0;           // 32768  A [128m,128k] fp16
static constexpr int SM_EB = 32768;       // 2 bufs x 33280
static constexpr int EB_E   = 0;          // 32768  E [128v,128d] fp16
static constexpr int EB_SCB = 32768;      // 512 (128 sc f16 + 128 bi f16)
static constexpr int EB_STRIDE = 33280;
static constexpr int SMEM_BYTES = 32768 + 2 * EB_STRIDE;  // 99328; x2/SM ok

// ---------------------------------------------------------------------------
__device__ __forceinline__ uint32_t s2u(const void* p) {
    uint32_t a;
    asm("{ .reg .u64 t; cvta.to.shared.u64 t, %1; cvt.u32.u64 %0, t; }" : "=r"(a) : "l"(p));
    return a;
}
// swizzled offsets: 16B chunks XOR'ed by (row & 7); rows of 128 f16 (256B)
__device__ __forceinline__ uint32_t off128(int r, int c) {
    return (uint32_t)(r * 256) + ((((c >> 3) ^ (r & 7)) << 4) | ((c & 7) * 2));
}
__device__ __forceinline__ void cpa16(uint32_t dst, const void* src, int srcsize) {
    asm volatile("cp.async.cg.shared.global [%0], [%1], 16, %2;"
                 :: "r"(dst), "l"(src), "r"(srcsize) : "memory");
}
__device__ __forceinline__ void cpa_commit() { asm volatile("cp.async.commit_group;" ::: "memory"); }
__device__ __forceinline__ void cpa_wait0()  { asm volatile("cp.async.wait_group 0;"  ::: "memory"); }

__device__ __forceinline__ void ldm4(uint32_t& r0, uint32_t& r1, uint32_t& r2, uint32_t& r3, uint32_t a) {
    asm volatile("ldmatrix.sync.aligned.m8n8.x4.shared.b16 {%0,%1,%2,%3}, [%4];"
                 : "=r"(r0), "=r"(r1), "=r"(r2), "=r"(r3) : "r"(a));
}
__device__ __forceinline__ void ldm4t(uint32_t& r0, uint32_t& r1, uint32_t& r2, uint32_t& r3, uint32_t a) {
    asm volatile("ldmatrix.sync.aligned.m8n8.x4.trans.shared.b16 {%0,%1,%2,%3}, [%4];"
                 : "=r"(r0), "=r"(r1), "=r"(r2), "=r"(r3) : "r"(a));
}
// f32-accumulator MMA (GEMM2)
__device__ __forceinline__ void mma16816h(float* d, const uint32_t* a, const uint32_t* b) {
    asm volatile("mma.sync.aligned.m16n8k16.row.col.f32.f16.f16.f32 "
                 "{%0,%1,%2,%3}, {%4,%5,%6,%7}, {%8,%9}, {%0,%1,%2,%3};"
                 : "+f"(d[0]), "+f"(d[1]), "+f"(d[2]), "+f"(d[3])
                 : "r"(a[0]), "r"(a[1]), "r"(a[2]), "r"(a[3]), "r"(b[0]), "r"(b[1]));
}
// f16-accumulator MMA (GEMM1): D regs are f16x2 {c0,c1},{c2,c3}
__device__ __forceinline__ void mma16816hh(uint32_t* d, const uint32_t* a, const uint32_t* b) {
    asm volatile("mma.sync.aligned.m16n8k16.row.col.f16.f16.f16.f16 "
                 "{%0,%1}, {%2,%3,%4,%5}, {%6,%7}, {%0,%1};"
                 : "+r"(d[0]), "+r"(d[1])
                 : "r"(a[0]), "r"(a[1]), "r"(a[2]), "r"(a[3]), "r"(b[0]), "r"(b[1]));
}
__device__ __forceinline__ void red_add_v2(float* p, float a, float b) {
    asm volatile("red.global.add.v2.f32 [%0], {%1, %2};" :: "l"(p), "f"(a), "f"(b) : "memory");
}
__device__ __forceinline__ void red_add_v4(float* p, float a, float b, float c, float d) {
    asm volatile("red.global.add.v4.f32 [%0], {%1, %2, %3, %4};"
                 :: "l"(p), "f"(a), "f"(b), "f"(c), "f"(d) : "memory");
}
__device__ __forceinline__ uint32_t pack_h2(float a, float b) {
    uint32_t p;
    asm("cvt.rn.f16x2.f32 %0, %1, %2;" : "=r"(p) : "f"(b), "f"(a));
    return p;
}
__device__ __forceinline__ float2 unpack_h2(uint32_t p) {
    __half2 h = *reinterpret_cast<__half2*>(&p);
    return __half22float2(h);
}
__device__ __forceinline__ uint32_t hfma2_relu(uint32_t s, uint32_t sc, uint32_t bi) {
    uint32_t d;
    asm("fma.rn.f16x2 %0, %1, %2, %3;" : "=r"(d) : "r"(s), "r"(sc), "r"(bi));
    asm("max.f16x2 %0, %0, %1;" : "+r"(d) : "r"(0u));
    return d;
}

// ---------------------------------------------------------------------------
// prepA: x/rel -> fp16, g_aggr = 0.1x, out = 0
static constexpr int PA_X = N_NODES * (DD / 2);   // 262144 f2 units
static constexpr int PA_R = N_REL * (DD / 2);     // 64000

__global__ void prepA_kernel(const float* __restrict__ x,
                             const float* __restrict__ rel,
                             float* __restrict__ out) {
    int i = blockIdx.x * blockDim.x + threadIdx.x;
    if (i >= PA_X) return;
    float2 v = ((const float2*)x)[i];
    ((uint32_t*)g_xh)[i] = pack_h2(v.x, v.y);
    ((float2*)g_aggr)[i] = make_float2(0.1f * v.x, 0.1f * v.y);
    ((float2*)out)[i] = make_float2(0.f, 0.f);
    if (i < PA_R) {
        float2 r = ((const float2*)rel)[i];
        ((uint32_t*)g_relh)[i] = pack_h2(r.x, r.y);
    }
}

// combo: scatter (blocks [0, SCAT_BLK)) + E/scale/bias fp16 convert (rest)
static constexpr int SCAT_BLK = N_EDGES * 32 / 256;   // 32768
static constexpr int CV_E  = N_ENT * (DD / 2);        // 3,200,000 u32 items
static constexpr int CV_SC = N_ENT / 2;               // 25,000
static constexpr int CV_TOT = CV_E + 2 * CV_SC;       // 3,250,000
static constexpr int CV_BLK = (CV_TOT + 255) / 256;   // 12696

__global__ void combo_kernel(const int* __restrict__ eidx,
                             const int* __restrict__ rid, const int* __restrict__ neg,
                             const float* __restrict__ eemb,
                             const float* __restrict__ scal,
                             const float* __restrict__ bias) {
    if (blockIdx.x < SCAT_BLK) {
        int gw = (blockIdx.x * blockDim.x + threadIdx.x) >> 5;
        int lane = threadIdx.x & 31;
        int src = eidx[gw], dst = eidx[N_EDGES + gw], r = rid[gw];
        float coef = 1.0f - 2.0f * (float)neg[gw];
        uint2 xv = ((const uint2*)(g_xh   + (size_t)src * DD))[lane];
        uint2 rv = ((const uint2*)(g_relh + (size_t)r   * DD))[lane];
        float2 x01 = unpack_h2(xv.x), x23 = unpack_h2(xv.y);
        float2 r01 = unpack_h2(rv.x), r23 = unpack_h2(rv.y);
        red_add_v4(g_aggr + (size_t)dst * DD + lane * 4,
                   (x01.x + r01.x) * coef, (x01.y + r01.y) * coef,
                   (x23.x + r23.x) * coef, (x23.y + r23.y) * coef);
    } else {
        int j = (blockIdx.x - SCAT_BLK) * 256 + threadIdx.x;
        if (j < CV_E) {
            float2 v = ((const float2*)eemb)[j];
            ((uint32_t*)g_Eh)[j] = pack_h2(v.x, v.y);
        } else if (j < CV_E + CV_SC) {
            int k = j - CV_E;
            float2 v = ((const float2*)scal)[k];
            ((uint32_t*)g_sch)[k] = pack_h2(v.x, v.y);
        } else if (j < CV_TOT) {
            int k = j - CV_E - CV_SC;
            float2 v = ((const float2*)bias)[k];
            ((uint32_t*)g_bih)[k] = pack_h2(v.x, v.y);
        }
    }
}

// ---------------------------------------------------------------------------
__global__ void __launch_bounds__(NTHR, 2)
gemm_fused(float* __restrict__ out) {
    extern __shared__ char smem[];
    const uint32_t sb = s2u(smem);
    const int tid = threadIdx.x, wid = tid >> 5, lane = tid & 31;
    const int mt = blockIdx.x & (MTILES - 1), sp = blockIdx.x / MTILES;
    const int m0 = mt * BM;
    const int t0 = sp * TPS, t1 = min(NVT, t0 + TPS);
    if (t0 >= t1) return;

    const int wm = wid * 32;               // warp owns rows [wm, wm+32): 2 m16

    auto load_tiles = [&](int t, int b) {
        const int v0 = t * BV;
        const uint32_t eb = sb + SM_EB + b * EB_STRIDE;
        for (int i = tid; i < 2048; i += NTHR) {    // E [128v,128d] fp16, 16B chunks
            int v = i >> 4, dg = (i & 15) * 8;
            int gv = v0 + v;
            uint32_t o = off128(v, dg);
            int sz = (gv < N_ENT) ? 16 : 0;
            const void* pE = sz ? (const void*)(g_Eh + (size_t)gv * DD + dg) : (const void*)g_Eh;
            cpa16(eb + EB_E + o, pE, sz);
        }
        if (tid < 32) {                              // 128 sc f16 + 128 bi f16
            int half = tid >> 4, g = tid & 15;       // 16 x 16B per array
            int gv = v0 + g * 8;
            int rem = N_ENT - gv;
            int sz = rem >= 8 ? 16 : (rem > 0 ? rem * 2 : 0);
            const __half* src = half ? g_bih : g_sch;
            const void* p = sz ? (const void*)(src + gv) : (const void*)src;
            cpa16(eb + EB_SCB + half * 256 + g * 16, p, sz);
        }
    };

    // issue tile-0 E loads first so they overlap the A staging below
    load_tiles(t0, 0);
    cpa_commit();

    // ---- A tile: g_aggr f32 -> fp16, swizzled (staged once) ----
    for (int i = tid; i < BM * (DD / 4); i += NTHR) {
        int m = i >> 5, k = (i & 31) * 4;
        float4 a = *(const float4*)(g_aggr + (size_t)(m0 + m) * DD + k);
        *(uint32_t*)(smem + SM_A + off128(m, k))     = pack_h2(a.x, a.y);
        *(uint32_t*)(smem + SM_A + off128(m, k + 2)) = pack_h2(a.z, a.w);
    }
    __syncthreads();

    // per-lane ldmatrix pieces (constant across loop)
    const int lr16 = lane & 15;            // row within 16
    const int lc8  = (lane >> 4) << 3;     // +8 col for upper half-warp
    const int lrB  = (lane & 7) | ((lane & 16) >> 1);  // B non-trans row
    const int lcB  = lane & 8;                          // B non-trans col sel
    const int ce   = (lane & 3) * 2;       // C/epilogue col pair base

    float accO[2][16][4];                   // 2 m16 x 128d per warp
    #pragma unroll
    for (int mi = 0; mi < 2; mi++)
        #pragma unroll
        for (int nt = 0; nt < 16; nt++)
            #pragma unroll
            for (int q = 0; q < 4; q++) accO[mi][nt][q] = 0.0f;

    for (int t = t0; t < t1; ++t) {
        const int buf = (t - t0) & 1;
        const uint32_t eb = sb + SM_EB + buf * EB_STRIDE;

        cpa_wait0();           // tile t landed (this thread's copies)
        __syncthreads();       // visible to all; all warps done with buf^1
        if (t + 1 < t1) { load_tiles(t + 1, buf ^ 1); cpa_commit(); }

        // -------- GEMM1: S[32m x 128v] per warp, fp16 accumulators ----------
        // accS[mi][j] covers v-cols [8j, 8j+8)
        uint32_t accS[2][16][2];
        #pragma unroll
        for (int mi = 0; mi < 2; mi++)
            #pragma unroll
            for (int j = 0; j < 16; j++)
                accS[mi][j][0] = accS[mi][j][1] = 0u;

        #pragma unroll
        for (int ks = 0; ks < 8; ks++) {
            const int k0 = ks * 16;
            uint32_t aA[2][4];
            #pragma unroll
            for (int mi = 0; mi < 2; mi++) {
                uint32_t o = off128(wm + mi * 16 + lr16, k0 + lc8);
                ldm4(aA[mi][0], aA[mi][1], aA[mi][2], aA[mi][3], sb + SM_A + o);
            }
            #pragma unroll
            for (int vh = 0; vh < 2; vh++) {
                uint32_t bF[8][2];
                #pragma unroll
                for (int ng = 0; ng < 4; ng++) {
                    uint32_t o = off128(vh * 64 + ng * 16 + lrB, k0 + lcB);
                    uint32_t r0, r1, r2, r3;
                    ldm4(r0, r1, r2, r3, eb + EB_E + o);
                    bF[ng * 2][0] = r0; bF[ng * 2][1] = r1;
                    bF[ng * 2 + 1][0] = r2; bF[ng * 2 + 1][1] = r3;
                }
                #pragma unroll
                for (int mi = 0; mi < 2; mi++)
                    #pragma unroll
                    for (int nt = 0; nt < 8; nt++)
                        mma16816hh(accS[mi][vh * 8 + nt], aA[mi], bF[nt]);
            }
        }

        // ---- per-g: packed f16x2 epilogue -> GEMM2 for that k16 group ------
        const __half* sch = (const __half*)(smem + SM_EB + buf * EB_STRIDE + EB_SCB);
        #pragma unroll
        for (int g = 0; g < 8; g++) {
            uint32_t aS[2][4];
            #pragma unroll
            for (int sub2 = 0; sub2 < 2; sub2++) {      // j = 2g, 2g+1
                const int j = 2 * g + sub2;
                const int c = j * 8 + ce;
                uint32_t sc2 = *(const uint32_t*)(sch + c);
                uint32_t bi2 = *(const uint32_t*)(sch + 128 + c);
                #pragma unroll
                for (int mi = 0; mi < 2; mi++) {
                    aS[mi][sub2 * 2]     = hfma2_relu(accS[mi][j][0], sc2, bi2);
                    aS[mi][sub2 * 2 + 1] = hfma2_relu(accS[mi][j][1], sc2, bi2);
                }
            }
            const int k0 = g * 16;
            #pragma unroll
            for (int half = 0; half < 2; half++) {
                uint32_t bF[8][2];
                #pragma unroll
                for (int ng = 0; ng < 4; ng++) {
                    uint32_t o = off128(k0 + lr16, half * 64 + ng * 16 + lc8);
                    uint32_t r0, r1, r2, r3;
                    ldm4t(r0, r1, r2, r3, eb + EB_E + o);
                    bF[ng * 2][0] = r0; bF[ng * 2][1] = r1;
                    bF[ng * 2 + 1][0] = r2; bF[ng * 2 + 1][1] = r3;
                }
                #pragma unroll
                for (int mi = 0; mi < 2; mi++)
                    #pragma unroll
                    for (int ng = 0; ng < 8; ng++)
                        mma16816h(accO[mi][half * 8 + ng], aS[mi], bF[ng]);
            }
        }
    }

    // ---- flush O to out (+= across splits) ----
    #pragma unroll
    for (int mi = 0; mi < 2; mi++) {
        const int r0 = m0 + wm + mi * 16 + (lane >> 2);
        #pragma unroll
        for (int nt = 0; nt < 16; nt++) {
            const int c = nt * 8 + ce;
            red_add_v2(out + (size_t)r0 * DD + c,       accO[mi][nt][0], accO[mi][nt][1]);
            red_add_v2(out + (size_t)(r0 + 8) * DD + c, accO[mi][nt][2], accO[mi][nt][3]);
        }
    }
}

// ---------------------------------------------------------------------------
extern "C" void kernel_launch(void* const* d_in, const int* in_sizes, int n_in,
                              void* d_out, int out_size) {
    const float* x     = (const float*)d_in[0];
    const int*   eidx  = (const int*)  d_in[1];
    const int*   rid   = (const int*)  d_in[2];
    const int*   neg   = (const int*)  d_in[3];
    const float* rel   = (const float*)d_in[4];
    const float* eemb  = (const float*)d_in[5];
    const float* scale = (const float*)d_in[6];
    const float* bias  = (const float*)d_in[7];
    float* out = (float*)d_out;

    cudaFuncSetAttribute(gemm_fused, cudaFuncAttributeMaxDynamicSharedMemorySize, SMEM_BYTES);

    prepA_kernel<<<(PA_X + 255) / 256, 256>>>(x, rel, out);
    combo_kernel<<<SCAT_BLK + CV_BLK, 256>>>(eidx, rid, neg, eemb, scale, bias);
    gemm_fused<<<MTILES * NSPLIT, NTHR, SMEM_BYTES>>>(out);
}